// round 1
// baseline (speedup 1.0000x reference)
#include <cuda_runtime.h>
#include <cuda_bf16.h>

#define N_NODES 20000
#define N_EDGES 200000
#define IN_DIM  500
#define HID     256
#define OUT_DIM 16
#define MHD     64

// ---------------- device scratch (static, no allocations) ----------------
__device__ float g_h  [N_NODES * HID];     // h, then xb (updated in place)
__device__ float g_h1 [N_NODES * MHD];     // MLP intermediates
__device__ float g_AB [N_NODES * 2 * MHD]; // [N][128]: A | B
__device__ float g_Wab[2 * MHD * HID];     // repacked Wm1 -> [128][256]
__device__ float g_PQS[(size_t)N_EDGES * 48]; // per-edge P(16) Q(16) S(16)
__device__ float g_H  [N_NODES * HID];     // diffusion operand H per layer
__device__ int   g_cnt[N_NODES];
__device__ int   g_off[N_NODES + 1];
__device__ int   g_cur[N_NODES];
__device__ int   g_incid[2 * N_EDGES];     // (e<<1)|role ; role 0=src,1=dst

// ---------------- generic SGEMM: C = act(A[M,K] @ W[N,K]^T + b) ----------
template<bool RELU>
__global__ __launch_bounds__(256)
void sgemm_rt(const float* __restrict__ A, const float* __restrict__ W,
              const float* __restrict__ bias, float* __restrict__ C,
              int M, int N, int K)
{
    __shared__ float As[16][68];
    __shared__ float Ws[16][68];
    int tid = threadIdx.x;
    int tx = tid & 15, ty = tid >> 4;
    int row0 = blockIdx.y * 64, col0 = blockIdx.x * 64;
    float acc[4][4] = {};

    for (int k0 = 0; k0 < K; k0 += 16) {
        // A tile: 64 rows x 16 k
        {
            int i = tid >> 2;
            int kb = (tid & 3) * 4;
            int r = row0 + i;
            #pragma unroll
            for (int u = 0; u < 4; u++) {
                int k = k0 + kb + u;
                As[kb + u][i] = (r < M && k < K) ? A[(size_t)r * K + k] : 0.f;
            }
        }
        // W tile: 64 cols x 16 k (W row-major [N,K])
        {
            int j = tid & 63;
            int kb = (tid >> 6) * 4;
            int c = col0 + j;
            #pragma unroll
            for (int u = 0; u < 4; u++) {
                int k = k0 + kb + u;
                Ws[kb + u][j] = (c < N && k < K) ? W[(size_t)c * K + k] : 0.f;
            }
        }
        __syncthreads();
        #pragma unroll
        for (int k = 0; k < 16; k++) {
            float a[4], b[4];
            #pragma unroll
            for (int i = 0; i < 4; i++) a[i] = As[k][ty * 4 + i];
            #pragma unroll
            for (int j = 0; j < 4; j++) b[j] = Ws[k][tx * 4 + j];
            #pragma unroll
            for (int i = 0; i < 4; i++)
                #pragma unroll
                for (int j = 0; j < 4; j++)
                    acc[i][j] += a[i] * b[j];
        }
        __syncthreads();
    }
    #pragma unroll
    for (int i = 0; i < 4; i++) {
        int r = row0 + ty * 4 + i;
        if (r >= M) continue;
        #pragma unroll
        for (int j = 0; j < 4; j++) {
            int c = col0 + tx * 4 + j;
            if (c >= N) continue;
            float v = acc[i][j] + (bias ? bias[c] : 0.f);
            if (RELU) v = fmaxf(v, 0.f);
            C[(size_t)r * N + c] = v;
        }
    }
}

// ---------------- CSR build ----------------
__global__ void count_kernel(const int* __restrict__ ei) {
    int e = blockIdx.x * 256 + threadIdx.x;
    if (e < N_EDGES) {
        atomicAdd(&g_cnt[ei[e]], 1);
        atomicAdd(&g_cnt[ei[N_EDGES + e]], 1);
    }
}

__global__ void scan_kernel() {
    const int CH = (N_NODES + 1023) / 1024;  // 20
    __shared__ int ssum[1024];
    int tid = threadIdx.x;
    int begin = tid * CH;
    int endi = begin + CH; if (endi > N_NODES) endi = N_NODES;
    int s = 0;
    for (int i = begin; i < endi; i++) s += g_cnt[i];
    ssum[tid] = s;
    __syncthreads();
    for (int off = 1; off < 1024; off <<= 1) {
        int v = 0;
        if (tid >= off) v = ssum[tid - off];
        __syncthreads();
        ssum[tid] += v;
        __syncthreads();
    }
    int run = ssum[tid] - s;   // exclusive base
    for (int i = begin; i < endi; i++) {
        g_off[i] = run;
        g_cur[i] = run;
        run += g_cnt[i];
    }
    if (tid == 1023) g_off[N_NODES] = ssum[1023];
}

__global__ void fill_kernel(const int* __restrict__ ei) {
    int e = blockIdx.x * 256 + threadIdx.x;
    if (e < N_EDGES) {
        int s = ei[e], d = ei[N_EDGES + e];
        int p = atomicAdd(&g_cur[s], 1);
        g_incid[p] = (e << 1);
        int p2 = atomicAdd(&g_cur[d], 1);
        g_incid[p2] = (e << 1) | 1;
    }
}

// ---------------- repack Wm1 into [128][256] ----------------
__global__ void repack_kernel(const float* __restrict__ Wm1) {
    int idx = blockIdx.x * 256 + threadIdx.x;   // < 32768
    int i = idx >> 8, k = idx & 255;
    g_Wab[idx] = (i < 64) ? Wm1[i * 512 + k] : Wm1[(i - 64) * 512 + 256 + k];
}

// ---------------- per-edge: t1/t2 -> Fs,Ft -> P,Q,S ----------------
__global__ __launch_bounds__(256)
void edge_kernel(const int* __restrict__ ei, const float* __restrict__ Wm2,
                 const float* __restrict__ bm1, const float* __restrict__ bm2)
{
    __shared__ float sbuf[8 * 160];  // per warp: t1[64] t2[64] fsft[32]
    int warp = threadIdx.x >> 5, lane = threadIdx.x & 31;
    int e = blockIdx.x * 8 + warp;   // grid 25000, exact
    float* sw = &sbuf[warp * 160];

    int s = ei[e], d = ei[N_EDGES + e];
    int k0 = lane * 2;
    float2 As = *(const float2*)&g_AB[s * 128 + k0];
    float2 Bd = *(const float2*)&g_AB[d * 128 + 64 + k0];
    float2 Ad = *(const float2*)&g_AB[d * 128 + k0];
    float2 Bs = *(const float2*)&g_AB[s * 128 + 64 + k0];
    float2 b1 = *(const float2*)&bm1[k0];
    sw[k0]       = fmaxf(As.x + Bd.x + b1.x, 0.f);
    sw[k0 + 1]   = fmaxf(As.y + Bd.y + b1.y, 0.f);
    sw[64 + k0]     = fmaxf(Ad.x + Bs.x + b1.x, 0.f);
    sw[64 + k0 + 1] = fmaxf(Ad.y + Bs.y + b1.y, 0.f);
    __syncwarp();

    // lanes 0-15 -> fs[o], lanes 16-31 -> ft[o]
    int o = lane & 15;
    const float* tv = sw + ((lane >> 4) << 6);
    float accf = 0.f;
    #pragma unroll
    for (int k = 0; k < 64; k += 4) {
        float4 t = *(const float4*)&tv[k];
        float4 w = *(const float4*)&Wm2[o * 64 + k];
        accf += t.x * w.x + t.y * w.y + t.z * w.z + t.w * w.w;
    }
    accf += bm2[o];
    sw[128 + lane] = accf;
    __syncwarp();

    if (lane < 16) {
        int i = lane >> 2, j = lane & 3;
        float p = 0.f, q = 0.f, ss = 0.f;
        #pragma unroll
        for (int m = 0; m < 4; m++) {
            float fsi = sw[128 + m * 4 + i], fsj = sw[128 + m * 4 + j];
            float fti = sw[144 + m * 4 + i], ftj = sw[144 + m * 4 + j];
            p  += fsi * fsj;   // P = Fs^T Fs
            q  += fsi * ftj;   // Q = Fs^T Ft
            ss += fti * ftj;   // S = Ft^T Ft
        }
        float* outp = &g_PQS[(size_t)e * 48];
        outp[lane]      = p;
        outp[16 + lane] = q;
        outp[32 + lane] = ss;
    }
}

// ---------------- per-node H = (Wd1^T @ xb) @ Wd2^T ----------------
__global__ __launch_bounds__(256)
void hcomp_kernel(const float* __restrict__ Wd1, const float* __restrict__ Wd2,
                  int layer)
{
    __shared__ float w2t[64][66];    // transposed Wd2[layer]
    __shared__ float h1s[8][4][64];
    int tid = threadIdx.x;
    for (int idx = tid; idx < 4096; idx += 256) {
        int g = idx >> 6, f = idx & 63;
        w2t[f][g] = Wd2[layer * 4096 + idx];
    }
    float wd1[16];
    #pragma unroll
    for (int i = 0; i < 16; i++) wd1[i] = __ldg(&Wd1[layer * 16 + i]);

    int warp = tid >> 5, lane = tid & 31;
    int n = blockIdx.x * 8 + warp;   // grid 2500, exact
    int c0 = lane * 2;
    float2 xv[4];
    #pragma unroll
    for (int j = 0; j < 4; j++)
        xv[j] = *(const float2*)&g_h[n * 256 + j * 64 + c0];
    #pragma unroll
    for (int i = 0; i < 4; i++) {
        h1s[warp][i][c0]     = wd1[i] * xv[0].x + wd1[4 + i] * xv[1].x +
                               wd1[8 + i] * xv[2].x + wd1[12 + i] * xv[3].x;
        h1s[warp][i][c0 + 1] = wd1[i] * xv[0].y + wd1[4 + i] * xv[1].y +
                               wd1[8 + i] * xv[2].y + wd1[12 + i] * xv[3].y;
    }
    __syncthreads();  // covers w2t load + h1s stores

    float2 acc[4] = {{0,0},{0,0},{0,0},{0,0}};
    #pragma unroll
    for (int f = 0; f < 64; f++) {
        float2 w = *(const float2*)&w2t[f][c0];
        #pragma unroll
        for (int k = 0; k < 4; k++) {
            float hv = h1s[warp][k][f];
            acc[k].x += hv * w.x;
            acc[k].y += hv * w.y;
        }
    }
    #pragma unroll
    for (int k = 0; k < 4; k++)
        *(float2*)&g_H[n * 256 + k * 64 + c0] = acc[k];
}

// ---------------- per-node gather: LH = D@H[n] - sum Qeff@H[other]; xb -= relu(LH)
__global__ __launch_bounds__(256)
void gather_kernel(const int* __restrict__ ei)
{
    int warp = threadIdx.x >> 5, lane = threadIdx.x & 31;
    int n = blockIdx.x * 8 + warp;   // grid 2500, exact
    int beg = g_off[n], endi = g_off[n + 1];
    int c0 = lane * 2;

    float4 aD[4] = {{0,0,0,0},{0,0,0,0},{0,0,0,0},{0,0,0,0}};
    float2 acc[4] = {{0,0},{0,0},{0,0},{0,0}};

    for (int idx = beg; idx < endi; idx++) {
        int v = __ldg(&g_incid[idx]);
        int e = v >> 1, role = v & 1;
        int other = role ? __ldg(&ei[e]) : __ldg(&ei[N_EDGES + e]);
        const float* base = &g_PQS[(size_t)e * 48];
        const float4* dg = (const float4*)(base + (role ? 32 : 0)); // P or S
        const float4* qq = (const float4*)(base + 16);              // Q
        float4 D0 = dg[0], D1 = dg[1], D2 = dg[2], D3 = dg[3];
        aD[0].x += D0.x; aD[0].y += D0.y; aD[0].z += D0.z; aD[0].w += D0.w;
        aD[1].x += D1.x; aD[1].y += D1.y; aD[1].z += D1.z; aD[1].w += D1.w;
        aD[2].x += D2.x; aD[2].y += D2.y; aD[2].z += D2.z; aD[2].w += D2.w;
        aD[3].x += D3.x; aD[3].y += D3.y; aD[3].z += D3.z; aD[3].w += D3.w;

        float4 Q0 = qq[0], Q1 = qq[1], Q2 = qq[2], Q3 = qq[3];
        float q00=Q0.x,q01=Q0.y,q02=Q0.z,q03=Q0.w;
        float q10=Q1.x,q11=Q1.y,q12=Q1.z,q13=Q1.w;
        float q20=Q2.x,q21=Q2.y,q22=Q2.z,q23=Q2.w;
        float q30=Q3.x,q31=Q3.y,q32=Q3.z,q33=Q3.w;
        if (role) {  // need Q^T
            float t;
            t=q01;q01=q10;q10=t; t=q02;q02=q20;q20=t; t=q03;q03=q30;q30=t;
            t=q12;q12=q21;q21=t; t=q13;q13=q31;q31=t; t=q23;q23=q32;q32=t;
        }
        const float* hb = &g_H[(size_t)other * 256 + c0];
        float2 h0 = *(const float2*)&hb[0];
        float2 h1 = *(const float2*)&hb[64];
        float2 h2 = *(const float2*)&hb[128];
        float2 h3 = *(const float2*)&hb[192];

        acc[0].x -= q00*h0.x + q01*h1.x + q02*h2.x + q03*h3.x;
        acc[0].y -= q00*h0.y + q01*h1.y + q02*h2.y + q03*h3.y;
        acc[1].x -= q10*h0.x + q11*h1.x + q12*h2.x + q13*h3.x;
        acc[1].y -= q10*h0.y + q11*h1.y + q12*h2.y + q13*h3.y;
        acc[2].x -= q20*h0.x + q21*h1.x + q22*h2.x + q23*h3.x;
        acc[2].y -= q20*h0.y + q21*h1.y + q22*h2.y + q23*h3.y;
        acc[3].x -= q30*h0.x + q31*h1.x + q32*h2.x + q33*h3.x;
        acc[3].y -= q30*h0.y + q31*h1.y + q32*h2.y + q33*h3.y;
    }

    const float* hnb = &g_H[(size_t)n * 256 + c0];
    float2 hn0 = *(const float2*)&hnb[0];
    float2 hn1 = *(const float2*)&hnb[64];
    float2 hn2 = *(const float2*)&hnb[128];
    float2 hn3 = *(const float2*)&hnb[192];

    #pragma unroll
    for (int i = 0; i < 4; i++) {
        float lx = acc[i].x + aD[i].x*hn0.x + aD[i].y*hn1.x + aD[i].z*hn2.x + aD[i].w*hn3.x;
        float ly = acc[i].y + aD[i].x*hn0.y + aD[i].y*hn1.y + aD[i].z*hn2.y + aD[i].w*hn3.y;
        float* xp = &g_h[(size_t)n * 256 + i * 64 + c0];
        float2 xv = *(const float2*)xp;
        xv.x -= fmaxf(lx, 0.f);
        xv.y -= fmaxf(ly, 0.f);
        *(float2*)xp = xv;
    }
}

// ---------------- launch ----------------
extern "C" void kernel_launch(void* const* d_in, const int* in_sizes, int n_in,
                              void* d_out, int out_size)
{
    const float* x    = (const float*)d_in[0];
    const int*   ei   = (const int*)  d_in[1];
    const float* Win1 = (const float*)d_in[2];
    const float* bin1 = (const float*)d_in[3];
    const float* Win2 = (const float*)d_in[4];
    const float* bin2 = (const float*)d_in[5];
    const float* Wm1  = (const float*)d_in[6];
    const float* bm1  = (const float*)d_in[7];
    const float* Wm2  = (const float*)d_in[8];
    const float* bm2  = (const float*)d_in[9];
    const float* Wd1  = (const float*)d_in[10];
    const float* Wd2  = (const float*)d_in[11];
    const float* Wo1  = (const float*)d_in[12];
    const float* bo1  = (const float*)d_in[13];
    const float* Wo2  = (const float*)d_in[14];
    const float* bo2  = (const float*)d_in[15];
    float* out = (float*)d_out;

    void *p_cnt, *p_h, *p_h1, *p_AB, *p_Wab;
    cudaGetSymbolAddress(&p_cnt, g_cnt);
    cudaGetSymbolAddress(&p_h,   g_h);
    cudaGetSymbolAddress(&p_h1,  g_h1);
    cudaGetSymbolAddress(&p_AB,  g_AB);
    cudaGetSymbolAddress(&p_Wab, g_Wab);
    float* h   = (float*)p_h;
    float* h1  = (float*)p_h1;
    float* AB  = (float*)p_AB;
    float* Wab = (float*)p_Wab;

    // CSR build
    cudaMemsetAsync(p_cnt, 0, N_NODES * sizeof(int), 0);
    count_kernel<<<(N_EDGES + 255) / 256, 256>>>(ei);
    scan_kernel<<<1, 1024>>>();
    fill_kernel<<<(N_EDGES + 255) / 256, 256>>>(ei);

    // weight repack
    repack_kernel<<<128, 256>>>(Wm1);

    const int MB = (N_NODES + 63) / 64;  // 313

    // input MLP: h1 = relu(x@Win1^T + bin1); h = h1@Win2^T + bin2
    sgemm_rt<true ><<<dim3(1, MB), 256>>>(x,  Win1, bin1, h1, N_NODES, 64,  IN_DIM);
    sgemm_rt<false><<<dim3(4, MB), 256>>>(h1, Win2, bin2, h,  N_NODES, 256, 64);

    // AB = h @ Wab^T  -> [N][128]
    sgemm_rt<false><<<dim3(2, MB), 256>>>(h, Wab, (const float*)nullptr, AB, N_NODES, 128, 256);

    // per-edge restriction products
    edge_kernel<<<N_EDGES / 8, 256>>>(ei, Wm2, bm1, bm2);

    // diffusion layers
    for (int l = 0; l < 2; l++) {
        hcomp_kernel<<<N_NODES / 8, 256>>>(Wd1, Wd2, l);
        gather_kernel<<<N_NODES / 8, 256>>>(ei);
    }

    // output MLP
    sgemm_rt<true ><<<dim3(1, MB), 256>>>(h,  Wo1, bo1, h1,  N_NODES, 64, 256);
    sgemm_rt<false><<<dim3(1, MB), 256>>>(h1, Wo2, bo2, out, N_NODES, 16, 64);
}

// round 2
// speedup vs baseline: 1.0484x; 1.0484x over previous
#include <cuda_runtime.h>
#include <cuda_bf16.h>

#define N_NODES 20000
#define N_EDGES 200000
#define IN_DIM  500
#define HID     256
#define OUT_DIM 16
#define MHD     64

// ---------------- device scratch (static, no allocations) ----------------
__device__ float g_h  [N_NODES * HID];     // h, then xb (updated in place)
__device__ float g_h1 [N_NODES * MHD];     // MLP intermediates
__device__ float g_AB [N_NODES * 2 * MHD]; // [N][128]: A | B
__device__ float g_Wc [2 * MHD * MHD];     // combined (Wab @ Win2) -> [128][64]
__device__ float g_bc [2 * MHD];           // combined bias Wab @ bin2
__device__ float g_PQS[(size_t)N_EDGES * 48]; // per-edge P(16) Q(16) S(16)
__device__ float g_H  [N_NODES * HID];     // diffusion operand H per layer
__device__ int   g_cnt[N_NODES];
__device__ int   g_off[N_NODES + 1];
__device__ int   g_cur[N_NODES];
__device__ int   g_incid[2 * N_EDGES];     // (e<<1)|role ; role 0=src,1=dst

// ---------------- SGEMM: C = act(A[M,K] @ W[N,K]^T + b) ------------------
// BM=128, BN=64, BK=16, 256 threads, 8x4 micro-tile, register prefetch.
template<bool RELU>
__global__ __launch_bounds__(256)
void sgemm128(const float* __restrict__ A, const float* __restrict__ W,
              const float* __restrict__ bias, float* __restrict__ C,
              int M, int N, int K)
{
    __shared__ float As[16][132];   // [k][m], 132*4=528B row (16B aligned)
    __shared__ float Ws[16][68];    // [k][n], 272B row (16B aligned)

    int tid = threadIdx.x;
    int tx = tid & 15, ty = tid >> 4;      // tx -> 4 cols, ty -> 8 rows
    int row0 = blockIdx.y * 128, col0 = blockIdx.x * 64;

    // load indices
    int arow = tid >> 1;            // 0..127
    int akb  = (tid & 1) * 8;       // 0 or 8
    int wcol = tid & 63;            // 0..63
    int wkb  = (tid >> 6) * 4;      // 0,4,8,12

    int gr = row0 + arow;
    int gc = col0 + wcol;
    const float* Arow = A + (size_t)(gr < M ? gr : 0) * K;
    const float* Wrow = W + (size_t)(gc < N ? gc : 0) * K;
    bool rok = gr < M;
    bool cok = gc < N;

    float acc[8][4] = {};
    float ra[8], rw[4];

    // preload tile 0
    #pragma unroll
    for (int u = 0; u < 8; u++) {
        int k = akb + u;
        ra[u] = (rok && k < K) ? Arow[k] : 0.f;
    }
    #pragma unroll
    for (int u = 0; u < 4; u++) {
        int k = wkb + u;
        rw[u] = (cok && k < K) ? Wrow[k] : 0.f;
    }

    for (int k0 = 0; k0 < K; k0 += 16) {
        #pragma unroll
        for (int u = 0; u < 8; u++) As[akb + u][arow] = ra[u];
        #pragma unroll
        for (int u = 0; u < 4; u++) Ws[wkb + u][wcol] = rw[u];
        __syncthreads();

        int kn = k0 + 16;
        if (kn < K) {
            #pragma unroll
            for (int u = 0; u < 8; u++) {
                int k = kn + akb + u;
                ra[u] = (rok && k < K) ? Arow[k] : 0.f;
            }
            #pragma unroll
            for (int u = 0; u < 4; u++) {
                int k = kn + wkb + u;
                rw[u] = (cok && k < K) ? Wrow[k] : 0.f;
            }
        }

        #pragma unroll
        for (int kk = 0; kk < 16; kk++) {
            float4 a0 = *(const float4*)&As[kk][ty * 8];
            float4 a1 = *(const float4*)&As[kk][ty * 8 + 4];
            float4 b0 = *(const float4*)&Ws[kk][tx * 4];
            float a[8] = {a0.x, a0.y, a0.z, a0.w, a1.x, a1.y, a1.z, a1.w};
            float b[4] = {b0.x, b0.y, b0.z, b0.w};
            #pragma unroll
            for (int i = 0; i < 8; i++)
                #pragma unroll
                for (int j = 0; j < 4; j++)
                    acc[i][j] += a[i] * b[j];
        }
        __syncthreads();
    }

    #pragma unroll
    for (int i = 0; i < 8; i++) {
        int r = row0 + ty * 8 + i;
        if (r >= M) continue;
        #pragma unroll
        for (int j = 0; j < 4; j++) {
            int c = col0 + tx * 4 + j;
            if (c >= N) continue;
            float v = acc[i][j] + (bias ? bias[c] : 0.f);
            if (RELU) v = fmaxf(v, 0.f);
            C[(size_t)r * N + c] = v;
        }
    }
}

// ---------------- CSR build ----------------
__global__ void count_kernel(const int* __restrict__ ei) {
    int e = blockIdx.x * 256 + threadIdx.x;
    if (e < N_EDGES) {
        atomicAdd(&g_cnt[ei[e]], 1);
        atomicAdd(&g_cnt[ei[N_EDGES + e]], 1);
    }
}

__global__ void scan_kernel() {
    const int CH = (N_NODES + 1023) / 1024;  // 20
    __shared__ int ssum[1024];
    int tid = threadIdx.x;
    int begin = tid * CH;
    int endi = begin + CH; if (endi > N_NODES) endi = N_NODES;
    int s = 0;
    for (int i = begin; i < endi; i++) s += g_cnt[i];
    ssum[tid] = s;
    __syncthreads();
    for (int off = 1; off < 1024; off <<= 1) {
        int v = 0;
        if (tid >= off) v = ssum[tid - off];
        __syncthreads();
        ssum[tid] += v;
        __syncthreads();
    }
    int run = ssum[tid] - s;   // exclusive base
    for (int i = begin; i < endi; i++) {
        g_off[i] = run;
        g_cur[i] = run;
        run += g_cnt[i];
    }
    if (tid == 1023) g_off[N_NODES] = ssum[1023];
}

__global__ void fill_kernel(const int* __restrict__ ei) {
    int e = blockIdx.x * 256 + threadIdx.x;
    if (e < N_EDGES) {
        int s = ei[e], d = ei[N_EDGES + e];
        int p = atomicAdd(&g_cur[s], 1);
        g_incid[p] = (e << 1);
        int p2 = atomicAdd(&g_cur[d], 1);
        g_incid[p2] = (e << 1) | 1;
    }
}

// ---------------- combined weights: Wc = Wab @ Win2, bc = Wab @ bin2 -----
// Wab[i][hid] = (i<64) ? Wm1[i][hid] : Wm1[i-64][256+hid]
// Win2 is [HID=256][MH=64] row-major. Wc[i][mh] = sum_hid Wab[i][hid]*Win2[hid][mh]
__global__ void wc_kernel(const float* __restrict__ Wm1,
                          const float* __restrict__ Win2,
                          const float* __restrict__ bin2)
{
    int idx = blockIdx.x * 256 + threadIdx.x;   // < 8192
    int i = idx >> 6, mh = idx & 63;
    const float* wrow = (i < 64) ? &Wm1[i * 512] : &Wm1[(i - 64) * 512 + 256];
    float s = 0.f;
    #pragma unroll 8
    for (int hid = 0; hid < 256; hid++)
        s += wrow[hid] * Win2[hid * 64 + mh];
    g_Wc[idx] = s;
    if (mh == 0) {
        float b = 0.f;
        for (int hid = 0; hid < 256; hid++) b += wrow[hid] * bin2[hid];
        g_bc[i] = b;
    }
}

// ---------------- per-edge: t1/t2 -> Fs,Ft -> P,Q,S ----------------
__global__ __launch_bounds__(256)
void edge_kernel(const int* __restrict__ ei, const float* __restrict__ Wm2,
                 const float* __restrict__ bm1, const float* __restrict__ bm2)
{
    __shared__ float sbuf[8 * 160];  // per warp: t1[64] t2[64] fsft[32]
    int warp = threadIdx.x >> 5, lane = threadIdx.x & 31;
    int e = blockIdx.x * 8 + warp;   // grid 25000, exact
    float* sw = &sbuf[warp * 160];

    int s = ei[e], d = ei[N_EDGES + e];
    int k0 = lane * 2;
    float2 As = *(const float2*)&g_AB[s * 128 + k0];
    float2 Bd = *(const float2*)&g_AB[d * 128 + 64 + k0];
    float2 Ad = *(const float2*)&g_AB[d * 128 + k0];
    float2 Bs = *(const float2*)&g_AB[s * 128 + 64 + k0];
    float2 b1 = *(const float2*)&bm1[k0];
    sw[k0]       = fmaxf(As.x + Bd.x + b1.x, 0.f);
    sw[k0 + 1]   = fmaxf(As.y + Bd.y + b1.y, 0.f);
    sw[64 + k0]     = fmaxf(Ad.x + Bs.x + b1.x, 0.f);
    sw[64 + k0 + 1] = fmaxf(Ad.y + Bs.y + b1.y, 0.f);
    __syncwarp();

    // lanes 0-15 -> fs[o], lanes 16-31 -> ft[o]
    int o = lane & 15;
    const float* tv = sw + ((lane >> 4) << 6);
    float accf = 0.f;
    #pragma unroll
    for (int k = 0; k < 64; k += 4) {
        float4 t = *(const float4*)&tv[k];
        float4 w = *(const float4*)&Wm2[o * 64 + k];
        accf += t.x * w.x + t.y * w.y + t.z * w.z + t.w * w.w;
    }
    accf += bm2[o];
    sw[128 + lane] = accf;
    __syncwarp();

    if (lane < 16) {
        int i = lane >> 2, j = lane & 3;
        float p = 0.f, q = 0.f, ss = 0.f;
        #pragma unroll
        for (int m = 0; m < 4; m++) {
            float fsi = sw[128 + m * 4 + i], fsj = sw[128 + m * 4 + j];
            float fti = sw[144 + m * 4 + i], ftj = sw[144 + m * 4 + j];
            p  += fsi * fsj;   // P = Fs^T Fs
            q  += fsi * ftj;   // Q = Fs^T Ft
            ss += fti * ftj;   // S = Ft^T Ft
        }
        float* outp = &g_PQS[(size_t)e * 48];
        outp[lane]      = p;
        outp[16 + lane] = q;
        outp[32 + lane] = ss;
    }
}

// ---------------- per-node H = (Wd1^T @ xb) @ Wd2^T ----------------
__global__ __launch_bounds__(256)
void hcomp_kernel(const float* __restrict__ Wd1, const float* __restrict__ Wd2,
                  int layer)
{
    __shared__ float w2t[64][66];    // transposed Wd2[layer]
    __shared__ float h1s[8][4][64];
    int tid = threadIdx.x;
    for (int idx = tid; idx < 4096; idx += 256) {
        int g = idx >> 6, f = idx & 63;
        w2t[f][g] = Wd2[layer * 4096 + idx];
    }
    float wd1[16];
    #pragma unroll
    for (int i = 0; i < 16; i++) wd1[i] = __ldg(&Wd1[layer * 16 + i]);

    int warp = tid >> 5, lane = tid & 31;
    int n = blockIdx.x * 8 + warp;   // grid 2500, exact
    int c0 = lane * 2;
    float2 xv[4];
    #pragma unroll
    for (int j = 0; j < 4; j++)
        xv[j] = *(const float2*)&g_h[n * 256 + j * 64 + c0];
    #pragma unroll
    for (int i = 0; i < 4; i++) {
        h1s[warp][i][c0]     = wd1[i] * xv[0].x + wd1[4 + i] * xv[1].x +
                               wd1[8 + i] * xv[2].x + wd1[12 + i] * xv[3].x;
        h1s[warp][i][c0 + 1] = wd1[i] * xv[0].y + wd1[4 + i] * xv[1].y +
                               wd1[8 + i] * xv[2].y + wd1[12 + i] * xv[3].y;
    }
    __syncthreads();  // covers w2t load + h1s stores

    float2 acc[4] = {{0,0},{0,0},{0,0},{0,0}};
    #pragma unroll
    for (int f = 0; f < 64; f++) {
        float2 w = *(const float2*)&w2t[f][c0];
        #pragma unroll
        for (int k = 0; k < 4; k++) {
            float hv = h1s[warp][k][f];
            acc[k].x += hv * w.x;
            acc[k].y += hv * w.y;
        }
    }
    #pragma unroll
    for (int k = 0; k < 4; k++)
        *(float2*)&g_H[n * 256 + k * 64 + c0] = acc[k];
}

// ---------------- per-node gather: LH = D@H[n] - sum Qeff@H[other]; xb -= relu(LH)
__global__ __launch_bounds__(256)
void gather_kernel(const int* __restrict__ ei)
{
    int warp = threadIdx.x >> 5, lane = threadIdx.x & 31;
    int n = blockIdx.x * 8 + warp;   // grid 2500, exact
    int beg = g_off[n], endi = g_off[n + 1];
    int c0 = lane * 2;

    float4 aD[4] = {{0,0,0,0},{0,0,0,0},{0,0,0,0},{0,0,0,0}};
    float2 acc[4] = {{0,0},{0,0},{0,0},{0,0}};

    for (int idx = beg; idx < endi; idx++) {
        int v = __ldg(&g_incid[idx]);
        int e = v >> 1, role = v & 1;
        int other = role ? __ldg(&ei[e]) : __ldg(&ei[N_EDGES + e]);
        const float* base = &g_PQS[(size_t)e * 48];
        const float4* dg = (const float4*)(base + (role ? 32 : 0)); // P or S
        const float4* qq = (const float4*)(base + 16);              // Q
        float4 D0 = dg[0], D1 = dg[1], D2 = dg[2], D3 = dg[3];
        aD[0].x += D0.x; aD[0].y += D0.y; aD[0].z += D0.z; aD[0].w += D0.w;
        aD[1].x += D1.x; aD[1].y += D1.y; aD[1].z += D1.z; aD[1].w += D1.w;
        aD[2].x += D2.x; aD[2].y += D2.y; aD[2].z += D2.z; aD[2].w += D2.w;
        aD[3].x += D3.x; aD[3].y += D3.y; aD[3].z += D3.z; aD[3].w += D3.w;

        float4 Q0 = qq[0], Q1 = qq[1], Q2 = qq[2], Q3 = qq[3];
        float q00=Q0.x,q01=Q0.y,q02=Q0.z,q03=Q0.w;
        float q10=Q1.x,q11=Q1.y,q12=Q1.z,q13=Q1.w;
        float q20=Q2.x,q21=Q2.y,q22=Q2.z,q23=Q2.w;
        float q30=Q3.x,q31=Q3.y,q32=Q3.z,q33=Q3.w;
        if (role) {  // need Q^T
            float t;
            t=q01;q01=q10;q10=t; t=q02;q02=q20;q20=t; t=q03;q03=q30;q30=t;
            t=q12;q12=q21;q21=t; t=q13;q13=q31;q31=t; t=q23;q23=q32;q32=t;
        }
        const float* hb = &g_H[(size_t)other * 256 + c0];
        float2 h0 = *(const float2*)&hb[0];
        float2 h1 = *(const float2*)&hb[64];
        float2 h2 = *(const float2*)&hb[128];
        float2 h3 = *(const float2*)&hb[192];

        acc[0].x -= q00*h0.x + q01*h1.x + q02*h2.x + q03*h3.x;
        acc[0].y -= q00*h0.y + q01*h1.y + q02*h2.y + q03*h3.y;
        acc[1].x -= q10*h0.x + q11*h1.x + q12*h2.x + q13*h3.x;
        acc[1].y -= q10*h0.y + q11*h1.y + q12*h2.y + q13*h3.y;
        acc[2].x -= q20*h0.x + q21*h1.x + q22*h2.x + q23*h3.x;
        acc[2].y -= q20*h0.y + q21*h1.y + q22*h2.y + q23*h3.y;
        acc[3].x -= q30*h0.x + q31*h1.x + q32*h2.x + q33*h3.x;
        acc[3].y -= q30*h0.y + q31*h1.y + q32*h2.y + q33*h3.y;
    }

    const float* hnb = &g_H[(size_t)n * 256 + c0];
    float2 hn0 = *(const float2*)&hnb[0];
    float2 hn1 = *(const float2*)&hnb[64];
    float2 hn2 = *(const float2*)&hnb[128];
    float2 hn3 = *(const float2*)&hnb[192];

    #pragma unroll
    for (int i = 0; i < 4; i++) {
        float lx = acc[i].x + aD[i].x*hn0.x + aD[i].y*hn1.x + aD[i].z*hn2.x + aD[i].w*hn3.x;
        float ly = acc[i].y + aD[i].x*hn0.y + aD[i].y*hn1.y + aD[i].z*hn2.y + aD[i].w*hn3.y;
        float* xp = &g_h[(size_t)n * 256 + i * 64 + c0];
        float2 xv = *(const float2*)xp;
        xv.x -= fmaxf(lx, 0.f);
        xv.y -= fmaxf(ly, 0.f);
        *(float2*)xp = xv;
    }
}

// ---------------- launch ----------------
extern "C" void kernel_launch(void* const* d_in, const int* in_sizes, int n_in,
                              void* d_out, int out_size)
{
    const float* x    = (const float*)d_in[0];
    const int*   ei   = (const int*)  d_in[1];
    const float* Win1 = (const float*)d_in[2];
    const float* bin1 = (const float*)d_in[3];
    const float* Win2 = (const float*)d_in[4];
    const float* bin2 = (const float*)d_in[5];
    const float* Wm1  = (const float*)d_in[6];
    const float* bm1  = (const float*)d_in[7];
    const float* Wm2  = (const float*)d_in[8];
    const float* bm2  = (const float*)d_in[9];
    const float* Wd1  = (const float*)d_in[10];
    const float* Wd2  = (const float*)d_in[11];
    const float* Wo1  = (const float*)d_in[12];
    const float* bo1  = (const float*)d_in[13];
    const float* Wo2  = (const float*)d_in[14];
    const float* bo2  = (const float*)d_in[15];
    float* out = (float*)d_out;

    void *p_cnt, *p_h, *p_h1, *p_AB, *p_Wc, *p_bc;
    cudaGetSymbolAddress(&p_cnt, g_cnt);
    cudaGetSymbolAddress(&p_h,   g_h);
    cudaGetSymbolAddress(&p_h1,  g_h1);
    cudaGetSymbolAddress(&p_AB,  g_AB);
    cudaGetSymbolAddress(&p_Wc,  g_Wc);
    cudaGetSymbolAddress(&p_bc,  g_bc);
    float* h   = (float*)p_h;
    float* h1  = (float*)p_h1;
    float* AB  = (float*)p_AB;
    float* Wc  = (float*)p_Wc;
    float* bc  = (float*)p_bc;

    // CSR build
    cudaMemsetAsync(p_cnt, 0, N_NODES * sizeof(int), 0);
    count_kernel<<<(N_EDGES + 255) / 256, 256>>>(ei);
    scan_kernel<<<1, 1024>>>();
    fill_kernel<<<(N_EDGES + 255) / 256, 256>>>(ei);

    // combined Wc = Wab @ Win2, bc = Wab @ bin2
    wc_kernel<<<32, 256>>>(Wm1, Win2, bin2);

    const int MB = (N_NODES + 127) / 128;  // 157

    // input MLP: h1 = relu(x@Win1^T + bin1); h = h1@Win2^T + bin2
    sgemm128<true ><<<dim3(1, MB), 256>>>(x,  Win1, bin1, h1, N_NODES, 64,  IN_DIM);
    sgemm128<false><<<dim3(4, MB), 256>>>(h1, Win2, bin2, h,  N_NODES, 256, 64);

    // AB = h1 @ Wc^T + bc  (== h @ Wab^T), K=64
    sgemm128<false><<<dim3(2, MB), 256>>>(h1, Wc, bc, AB, N_NODES, 128, 64);

    // per-edge restriction products
    edge_kernel<<<N_EDGES / 8, 256>>>(ei, Wm2, bm1, bm2);

    // diffusion layers
    for (int l = 0; l < 2; l++) {
        hcomp_kernel<<<N_NODES / 8, 256>>>(Wd1, Wd2, l);
        gather_kernel<<<N_NODES / 8, 256>>>(ei);
    }

    // output MLP
    sgemm128<true ><<<dim3(1, MB), 256>>>(h,  Wo1, bo1, h1,  N_NODES, 64, 256);
    sgemm128<false><<<dim3(1, MB), 256>>>(h1, Wo2, bo2, out, N_NODES, 16, 64);
}

// round 3
// speedup vs baseline: 1.1807x; 1.1262x over previous
#include <cuda_runtime.h>
#include <cuda_bf16.h>

#define N_NODES 20000
#define N_EDGES 200000
#define IN_DIM  500
#define HID     256
#define OUT_DIM 16
#define MHD     64

// ---------------- device scratch (static, no allocations) ----------------
struct ZS {                     // zeroed by ONE memset each launch
    int   cnt[N_NODES];
    float D[N_NODES * 16];      // per-node sum of P (as src) + S (as dst)
};
__device__ ZS    g_zs;
__device__ float g_h  [N_NODES * HID];     // h, then xb (updated in place)
__device__ float g_h1 [N_NODES * MHD];     // MLP intermediates
__device__ float g_AB [N_NODES * 2 * MHD]; // [N][128]: A | B
__device__ float g_Wc [2 * MHD * MHD];     // combined (Wab @ Win2) -> [128][64]
__device__ float g_bc [2 * MHD];           // combined bias Wab @ bin2
__device__ float g_Q  [(size_t)N_EDGES * 16]; // per-edge Q = Fs^T Ft
__device__ float g_H  [N_NODES * HID];     // diffusion operand H per layer
__device__ int   g_off[N_NODES + 1];
__device__ int   g_cur[N_NODES];
__device__ int   g_incid[2 * N_EDGES];     // (e<<1)|role ; role 0=src,1=dst

// ---------------- SGEMM: C = act(A[M,K] @ W[N,K]^T + b) ------------------
// BM=128, BN=64, BK=16, 256 threads, 8x4 micro-tile, register prefetch.
template<bool RELU>
__global__ __launch_bounds__(256)
void sgemm128(const float* __restrict__ A, const float* __restrict__ W,
              const float* __restrict__ bias, float* __restrict__ C,
              int M, int N, int K)
{
    __shared__ float As[16][132];
    __shared__ float Ws[16][68];

    int tid = threadIdx.x;
    int tx = tid & 15, ty = tid >> 4;
    int row0 = blockIdx.y * 128, col0 = blockIdx.x * 64;

    int arow = tid >> 1;
    int akb  = (tid & 1) * 8;
    int wcol = tid & 63;
    int wkb  = (tid >> 6) * 4;

    int gr = row0 + arow;
    int gc = col0 + wcol;
    const float* Arow = A + (size_t)(gr < M ? gr : 0) * K;
    const float* Wrow = W + (size_t)(gc < N ? gc : 0) * K;
    bool rok = gr < M;
    bool cok = gc < N;

    float acc[8][4] = {};
    float ra[8], rw[4];

    #pragma unroll
    for (int u = 0; u < 8; u++) {
        int k = akb + u;
        ra[u] = (rok && k < K) ? Arow[k] : 0.f;
    }
    #pragma unroll
    for (int u = 0; u < 4; u++) {
        int k = wkb + u;
        rw[u] = (cok && k < K) ? Wrow[k] : 0.f;
    }

    for (int k0 = 0; k0 < K; k0 += 16) {
        #pragma unroll
        for (int u = 0; u < 8; u++) As[akb + u][arow] = ra[u];
        #pragma unroll
        for (int u = 0; u < 4; u++) Ws[wkb + u][wcol] = rw[u];
        __syncthreads();

        int kn = k0 + 16;
        if (kn < K) {
            #pragma unroll
            for (int u = 0; u < 8; u++) {
                int k = kn + akb + u;
                ra[u] = (rok && k < K) ? Arow[k] : 0.f;
            }
            #pragma unroll
            for (int u = 0; u < 4; u++) {
                int k = kn + wkb + u;
                rw[u] = (cok && k < K) ? Wrow[k] : 0.f;
            }
        }

        #pragma unroll
        for (int kk = 0; kk < 16; kk++) {
            float4 a0 = *(const float4*)&As[kk][ty * 8];
            float4 a1 = *(const float4*)&As[kk][ty * 8 + 4];
            float4 b0 = *(const float4*)&Ws[kk][tx * 4];
            float a[8] = {a0.x, a0.y, a0.z, a0.w, a1.x, a1.y, a1.z, a1.w};
            float b[4] = {b0.x, b0.y, b0.z, b0.w};
            #pragma unroll
            for (int i = 0; i < 8; i++)
                #pragma unroll
                for (int j = 0; j < 4; j++)
                    acc[i][j] += a[i] * b[j];
        }
        __syncthreads();
    }

    #pragma unroll
    for (int i = 0; i < 8; i++) {
        int r = row0 + ty * 8 + i;
        if (r >= M) continue;
        #pragma unroll
        for (int j = 0; j < 4; j++) {
            int c = col0 + tx * 4 + j;
            if (c >= N) continue;
            float v = acc[i][j] + (bias ? bias[c] : 0.f);
            if (RELU) v = fmaxf(v, 0.f);
            C[(size_t)r * N + c] = v;
        }
    }
}

// ---------------- CSR build ----------------
__global__ void count_kernel(const int* __restrict__ ei) {
    int e = blockIdx.x * 256 + threadIdx.x;
    if (e < N_EDGES) {
        atomicAdd(&g_zs.cnt[ei[e]], 1);
        atomicAdd(&g_zs.cnt[ei[N_EDGES + e]], 1);
    }
}

__global__ void scan_kernel() {
    const int CH = (N_NODES + 1023) / 1024;  // 20
    __shared__ int ssum[1024];
    int tid = threadIdx.x;
    int begin = tid * CH;
    int endi = begin + CH; if (endi > N_NODES) endi = N_NODES;
    int s = 0;
    for (int i = begin; i < endi; i++) s += g_zs.cnt[i];
    ssum[tid] = s;
    __syncthreads();
    for (int off = 1; off < 1024; off <<= 1) {
        int v = 0;
        if (tid >= off) v = ssum[tid - off];
        __syncthreads();
        ssum[tid] += v;
        __syncthreads();
    }
    int run = ssum[tid] - s;
    for (int i = begin; i < endi; i++) {
        g_off[i] = run;
        g_cur[i] = run;
        run += g_zs.cnt[i];
    }
    if (tid == 1023) g_off[N_NODES] = ssum[1023];
}

__global__ void fill_kernel(const int* __restrict__ ei) {
    int e = blockIdx.x * 256 + threadIdx.x;
    if (e < N_EDGES) {
        int s = ei[e], d = ei[N_EDGES + e];
        int p = atomicAdd(&g_cur[s], 1);
        g_incid[p] = (e << 1);
        int p2 = atomicAdd(&g_cur[d], 1);
        g_incid[p2] = (e << 1) | 1;
    }
}

// ---------------- combined weights: Wc = Wab @ Win2, bc = Wab @ bin2 -----
__global__ __launch_bounds__(256)
void wc_kernel(const float* __restrict__ Wm1,
               const float* __restrict__ Win2,
               const float* __restrict__ bin2)
{
    __shared__ float part[256];
    __shared__ float bpart[64];
    int i = blockIdx.x;                  // 0..127
    const float* wrow = (i < 64) ? &Wm1[i * 512] : &Wm1[(i - 64) * 512 + 256];
    int t = threadIdx.x;
    int mh = t & 63, kq = t >> 6;        // 4 chunks of 64 k's
    float s = 0.f;
    #pragma unroll 16
    for (int k = kq * 64; k < kq * 64 + 64; k++)
        s += wrow[k] * Win2[k * 64 + mh];
    part[t] = s;
    if (kq == 0) {
        float b = 0.f;
        #pragma unroll
        for (int k = mh * 4; k < mh * 4 + 4; k++) b += wrow[k] * bin2[k];
        bpart[mh] = b;
    }
    __syncthreads();
    if (kq == 0)
        g_Wc[i * 64 + mh] = part[mh] + part[64 + mh] + part[128 + mh] + part[192 + mh];
    if (t == 0) {
        float bb = 0.f;
        #pragma unroll
        for (int k = 0; k < 64; k++) bb += bpart[k];
        g_bc[i] = bb;
    }
}

// ---------------- per-edge: t1/t2 -> Fs,Ft -> Q stored; P,S atomically into D
__global__ __launch_bounds__(256)
void edge_kernel(const int* __restrict__ ei, const float* __restrict__ Wm2,
                 const float* __restrict__ bm1, const float* __restrict__ bm2)
{
    __shared__ float sbuf[8 * 160];
    int warp = threadIdx.x >> 5, lane = threadIdx.x & 31;
    int e = blockIdx.x * 8 + warp;   // grid 25000, exact
    float* sw = &sbuf[warp * 160];

    int s = ei[e], d = ei[N_EDGES + e];
    int k0 = lane * 2;
    float2 As = *(const float2*)&g_AB[s * 128 + k0];
    float2 Bd = *(const float2*)&g_AB[d * 128 + 64 + k0];
    float2 Ad = *(const float2*)&g_AB[d * 128 + k0];
    float2 Bs = *(const float2*)&g_AB[s * 128 + 64 + k0];
    float2 b1 = *(const float2*)&bm1[k0];
    sw[k0]          = fmaxf(As.x + Bd.x + b1.x, 0.f);
    sw[k0 + 1]      = fmaxf(As.y + Bd.y + b1.y, 0.f);
    sw[64 + k0]     = fmaxf(Ad.x + Bs.x + b1.x, 0.f);
    sw[64 + k0 + 1] = fmaxf(Ad.y + Bs.y + b1.y, 0.f);
    __syncwarp();

    int o = lane & 15;
    const float* tv = sw + ((lane >> 4) << 6);
    float accf = 0.f;
    #pragma unroll
    for (int k = 0; k < 64; k += 4) {
        float4 t = *(const float4*)&tv[k];
        float4 w = *(const float4*)&Wm2[o * 64 + k];
        accf += t.x * w.x + t.y * w.y + t.z * w.z + t.w * w.w;
    }
    accf += bm2[o];
    sw[128 + lane] = accf;
    __syncwarp();

    if (lane < 16) {
        int i = lane >> 2, j = lane & 3;
        float p = 0.f, q = 0.f, ss = 0.f;
        #pragma unroll
        for (int m = 0; m < 4; m++) {
            float fsi = sw[128 + m * 4 + i], fsj = sw[128 + m * 4 + j];
            float fti = sw[144 + m * 4 + i], ftj = sw[144 + m * 4 + j];
            p  += fsi * fsj;   // P = Fs^T Fs
            q  += fsi * ftj;   // Q = Fs^T Ft
            ss += fti * ftj;   // S = Ft^T Ft
        }
        g_Q[(size_t)e * 16 + lane] = q;
        atomicAdd(&g_zs.D[s * 16 + lane], p);
        atomicAdd(&g_zs.D[d * 16 + lane], ss);
    }
}

// ---------------- per-node H = (Wd1^T @ xb) @ Wd2^T ----------------
__global__ __launch_bounds__(256)
void hcomp_kernel(const float* __restrict__ Wd1, const float* __restrict__ Wd2,
                  int layer)
{
    __shared__ float w2t[64][66];
    __shared__ float h1s[8][4][64];
    int tid = threadIdx.x;
    for (int idx = tid; idx < 4096; idx += 256) {
        int g = idx >> 6, f = idx & 63;
        w2t[f][g] = Wd2[layer * 4096 + idx];
    }
    float wd1[16];
    #pragma unroll
    for (int i = 0; i < 16; i++) wd1[i] = __ldg(&Wd1[layer * 16 + i]);

    int warp = tid >> 5, lane = tid & 31;
    int n = blockIdx.x * 8 + warp;   // grid 2500, exact
    int c0 = lane * 2;
    float2 xv[4];
    #pragma unroll
    for (int j = 0; j < 4; j++)
        xv[j] = *(const float2*)&g_h[n * 256 + j * 64 + c0];
    #pragma unroll
    for (int i = 0; i < 4; i++) {
        h1s[warp][i][c0]     = wd1[i] * xv[0].x + wd1[4 + i] * xv[1].x +
                               wd1[8 + i] * xv[2].x + wd1[12 + i] * xv[3].x;
        h1s[warp][i][c0 + 1] = wd1[i] * xv[0].y + wd1[4 + i] * xv[1].y +
                               wd1[8 + i] * xv[2].y + wd1[12 + i] * xv[3].y;
    }
    __syncthreads();

    float2 acc[4] = {{0,0},{0,0},{0,0},{0,0}};
    #pragma unroll
    for (int f = 0; f < 64; f++) {
        float2 w = *(const float2*)&w2t[f][c0];
        #pragma unroll
        for (int k = 0; k < 4; k++) {
            float hv = h1s[warp][k][f];
            acc[k].x += hv * w.x;
            acc[k].y += hv * w.y;
        }
    }
    #pragma unroll
    for (int k = 0; k < 4; k++)
        *(float2*)&g_H[n * 256 + k * 64 + c0] = acc[k];
}

// ---------------- gather: one incidence contribution -> acc -= Qeff @ H[other]
__device__ __forceinline__ void proc_inc(int idx, const int* __restrict__ ei,
                                         int c0, float2 acc[4])
{
    int v = __ldg(&g_incid[idx]);
    int e = v >> 1, role = v & 1;
    int other = __ldg(&ei[role ? e : (N_EDGES + e)]);
    const float4* qq = (const float4*)&g_Q[(size_t)e * 16];
    float4 Q0 = qq[0], Q1 = qq[1], Q2 = qq[2], Q3 = qq[3];
    // role==1 uses Q^T
    float q00 = Q0.x, q11 = Q1.y, q22 = Q2.z, q33 = Q3.w;
    float q01 = role ? Q1.x : Q0.y;
    float q10 = role ? Q0.y : Q1.x;
    float q02 = role ? Q2.x : Q0.z;
    float q20 = role ? Q0.z : Q2.x;
    float q03 = role ? Q3.x : Q0.w;
    float q30 = role ? Q0.w : Q3.x;
    float q12 = role ? Q2.y : Q1.z;
    float q21 = role ? Q1.z : Q2.y;
    float q13 = role ? Q3.y : Q1.w;
    float q31 = role ? Q1.w : Q3.y;
    float q23 = role ? Q3.z : Q2.w;
    float q32 = role ? Q2.w : Q3.z;

    const float* hb = &g_H[(size_t)other * 256 + c0];
    float2 h0 = *(const float2*)&hb[0];
    float2 h1 = *(const float2*)&hb[64];
    float2 h2 = *(const float2*)&hb[128];
    float2 h3 = *(const float2*)&hb[192];

    acc[0].x -= q00*h0.x + q01*h1.x + q02*h2.x + q03*h3.x;
    acc[0].y -= q00*h0.y + q01*h1.y + q02*h2.y + q03*h3.y;
    acc[1].x -= q10*h0.x + q11*h1.x + q12*h2.x + q13*h3.x;
    acc[1].y -= q10*h0.y + q11*h1.y + q12*h2.y + q13*h3.y;
    acc[2].x -= q20*h0.x + q21*h1.x + q22*h2.x + q23*h3.x;
    acc[2].y -= q20*h0.y + q21*h1.y + q22*h2.y + q23*h3.y;
    acc[3].x -= q30*h0.x + q31*h1.x + q32*h2.x + q33*h3.x;
    acc[3].y -= q30*h0.y + q31*h1.y + q32*h2.y + q33*h3.y;
}

// 2 warps per node, 4 nodes per block; D applied from precomputed g_zs.D
__global__ __launch_bounds__(256)
void gather_kernel(const int* __restrict__ ei)
{
    __shared__ float red[4][256];
    int warp = threadIdx.x >> 5, lane = threadIdx.x & 31;
    int slot = warp >> 1, w2 = warp & 1;
    int n = blockIdx.x * 4 + slot;   // grid 5000, exact
    int beg = g_off[n], endi = g_off[n + 1];
    int cnt = endi - beg;
    int mid = beg + ((cnt + 1) >> 1);
    int lo = w2 ? mid : beg;
    int hi = w2 ? endi : mid;
    int c0 = lane * 2;

    float2 acc[4] = {{0,0},{0,0},{0,0},{0,0}};

    int idx = lo;
    for (; idx + 1 < hi; idx += 2) {   // two independent chains per iter
        proc_inc(idx,     ei, c0, acc);
        proc_inc(idx + 1, ei, c0, acc);
    }
    if (idx < hi) proc_inc(idx, ei, c0, acc);

    if (w2) {
        #pragma unroll
        for (int k = 0; k < 4; k++) {
            red[slot][k * 64 + c0]     = acc[k].x;
            red[slot][k * 64 + c0 + 1] = acc[k].y;
        }
    }
    __syncthreads();
    if (!w2) {
        const float4* Dp = (const float4*)&g_zs.D[n * 16];
        float4 D0 = Dp[0], D1 = Dp[1], D2 = Dp[2], D3 = Dp[3];
        const float* hnb = &g_H[(size_t)n * 256 + c0];
        float2 hn0 = *(const float2*)&hnb[0];
        float2 hn1 = *(const float2*)&hnb[64];
        float2 hn2 = *(const float2*)&hnb[128];
        float2 hn3 = *(const float2*)&hnb[192];
        float4 Dk[4] = {D0, D1, D2, D3};
        #pragma unroll
        for (int k = 0; k < 4; k++) {
            float lx = acc[k].x + red[slot][k * 64 + c0]
                     + Dk[k].x*hn0.x + Dk[k].y*hn1.x + Dk[k].z*hn2.x + Dk[k].w*hn3.x;
            float ly = acc[k].y + red[slot][k * 64 + c0 + 1]
                     + Dk[k].x*hn0.y + Dk[k].y*hn1.y + Dk[k].z*hn2.y + Dk[k].w*hn3.y;
            float* xp = &g_h[(size_t)n * 256 + k * 64 + c0];
            float2 xv = *(const float2*)xp;
            xv.x -= fmaxf(lx, 0.f);
            xv.y -= fmaxf(ly, 0.f);
            *(float2*)xp = xv;
        }
    }
}

// ---------------- launch ----------------
extern "C" void kernel_launch(void* const* d_in, const int* in_sizes, int n_in,
                              void* d_out, int out_size)
{
    const float* x    = (const float*)d_in[0];
    const int*   ei   = (const int*)  d_in[1];
    const float* Win1 = (const float*)d_in[2];
    const float* bin1 = (const float*)d_in[3];
    const float* Win2 = (const float*)d_in[4];
    const float* bin2 = (const float*)d_in[5];
    const float* Wm1  = (const float*)d_in[6];
    const float* bm1  = (const float*)d_in[7];
    const float* Wm2  = (const float*)d_in[8];
    const float* bm2  = (const float*)d_in[9];
    const float* Wd1  = (const float*)d_in[10];
    const float* Wd2  = (const float*)d_in[11];
    const float* Wo1  = (const float*)d_in[12];
    const float* bo1  = (const float*)d_in[13];
    const float* Wo2  = (const float*)d_in[14];
    const float* bo2  = (const float*)d_in[15];
    float* out = (float*)d_out;

    void *p_zs, *p_h, *p_h1, *p_AB, *p_Wc, *p_bc;
    cudaGetSymbolAddress(&p_zs, g_zs);
    cudaGetSymbolAddress(&p_h,  g_h);
    cudaGetSymbolAddress(&p_h1, g_h1);
    cudaGetSymbolAddress(&p_AB, g_AB);
    cudaGetSymbolAddress(&p_Wc, g_Wc);
    cudaGetSymbolAddress(&p_bc, g_bc);
    float* h   = (float*)p_h;
    float* h1  = (float*)p_h1;
    float* AB  = (float*)p_AB;
    float* Wc  = (float*)p_Wc;
    float* bc  = (float*)p_bc;

    const int MB = (N_NODES + 127) / 128;  // 157

    // slot 1: combined weights
    wc_kernel<<<128, 256>>>(Wm1, Win2, bin2);
    // slot 2: h1 = relu(x@Win1^T + bin1)
    sgemm128<true ><<<dim3(1, MB), 256>>>(x, Win1, bin1, h1, N_NODES, 64, IN_DIM);
    // slot 3: zero cnt + D
    cudaMemsetAsync(p_zs, 0, sizeof(ZS), 0);
    // slot 4: AB = h1 @ Wc^T + bc
    sgemm128<false><<<dim3(2, MB), 256>>>(h1, Wc, bc, AB, N_NODES, 128, 64);
    // slot 5 (PROFILED): per-edge Q + D atomics
    edge_kernel<<<N_EDGES / 8, 256>>>(ei, Wm2, bm1, bm2);

    // CSR build
    count_kernel<<<(N_EDGES + 255) / 256, 256>>>(ei);
    scan_kernel<<<1, 1024>>>();
    fill_kernel<<<(N_EDGES + 255) / 256, 256>>>(ei);

    // h = h1@Win2^T + bin2
    sgemm128<false><<<dim3(4, MB), 256>>>(h1, Win2, bin2, h, N_NODES, 256, 64);

    // diffusion layers
    for (int l = 0; l < 2; l++) {
        hcomp_kernel<<<N_NODES / 8, 256>>>(Wd1, Wd2, l);
        gather_kernel<<<N_NODES / 4, 256>>>(ei);
    }

    // output MLP
    sgemm128<true ><<<dim3(1, MB), 256>>>(h,  Wo1, bo1, h1,  N_NODES, 64, 256);
    sgemm128<false><<<dim3(1, MB), 256>>>(h1, Wo2, bo2, out, N_NODES, 16, 64);
}

// round 4
// speedup vs baseline: 1.7436x; 1.4768x over previous
#include <cuda_runtime.h>
#include <cuda_bf16.h>

#define N_NODES 20000
#define N_EDGES 200000
#define IN_DIM  500
#define HID     256
#define OUT_DIM 16
#define MHD     64

// ---------------- device scratch (static, no allocations) ----------------
struct ZS {                     // zeroed by ONE memset each launch
    int   cnt[N_NODES];
    float D[N_NODES * 16];      // per-node sum of P (as src) + S (as dst)
};
__device__ ZS    g_zs;
__device__ float g_h  [N_NODES * HID];     // h, then xb (updated in place)
__device__ float g_h1 [N_NODES * MHD];     // MLP intermediates
__device__ float g_AB [N_NODES * 2 * MHD]; // [N][128]: A | B
__device__ float g_Wc [2 * MHD * MHD];     // combined (Wab @ Win2) -> [128][64]
__device__ float g_bc [2 * MHD];           // combined bias Wab @ bin2
__device__ float g_Q  [(size_t)N_EDGES * 16]; // per-edge Q = Fs^T Ft
__device__ float g_H  [N_NODES * HID];     // diffusion operand H per layer
__device__ int   g_off[N_NODES + 1];
__device__ int   g_cur[N_NODES];
__device__ int   g_incid[2 * N_EDGES];     // (e<<1)|role ; role 0=src,1=dst

// ---------------- SGEMM: C = act(A[M,K] @ W[N,K]^T + b) ------------------
template<bool RELU>
__global__ __launch_bounds__(256)
void sgemm128(const float* __restrict__ A, const float* __restrict__ W,
              const float* __restrict__ bias, float* __restrict__ C,
              int M, int N, int K)
{
    __shared__ float As[16][132];
    __shared__ float Ws[16][68];

    int tid = threadIdx.x;
    int tx = tid & 15, ty = tid >> 4;
    int row0 = blockIdx.y * 128, col0 = blockIdx.x * 64;

    int arow = tid >> 1;
    int akb  = (tid & 1) * 8;
    int wcol = tid & 63;
    int wkb  = (tid >> 6) * 4;

    int gr = row0 + arow;
    int gc = col0 + wcol;
    const float* Arow = A + (size_t)(gr < M ? gr : 0) * K;
    const float* Wrow = W + (size_t)(gc < N ? gc : 0) * K;
    bool rok = gr < M;
    bool cok = gc < N;

    float acc[8][4] = {};
    float ra[8], rw[4];

    #pragma unroll
    for (int u = 0; u < 8; u++) {
        int k = akb + u;
        ra[u] = (rok && k < K) ? Arow[k] : 0.f;
    }
    #pragma unroll
    for (int u = 0; u < 4; u++) {
        int k = wkb + u;
        rw[u] = (cok && k < K) ? Wrow[k] : 0.f;
    }

    for (int k0 = 0; k0 < K; k0 += 16) {
        #pragma unroll
        for (int u = 0; u < 8; u++) As[akb + u][arow] = ra[u];
        #pragma unroll
        for (int u = 0; u < 4; u++) Ws[wkb + u][wcol] = rw[u];
        __syncthreads();

        int kn = k0 + 16;
        if (kn < K) {
            #pragma unroll
            for (int u = 0; u < 8; u++) {
                int k = kn + akb + u;
                ra[u] = (rok && k < K) ? Arow[k] : 0.f;
            }
            #pragma unroll
            for (int u = 0; u < 4; u++) {
                int k = kn + wkb + u;
                rw[u] = (cok && k < K) ? Wrow[k] : 0.f;
            }
        }

        #pragma unroll
        for (int kk = 0; kk < 16; kk++) {
            float4 a0 = *(const float4*)&As[kk][ty * 8];
            float4 a1 = *(const float4*)&As[kk][ty * 8 + 4];
            float4 b0 = *(const float4*)&Ws[kk][tx * 4];
            float a[8] = {a0.x, a0.y, a0.z, a0.w, a1.x, a1.y, a1.z, a1.w};
            float b[4] = {b0.x, b0.y, b0.z, b0.w};
            #pragma unroll
            for (int i = 0; i < 8; i++)
                #pragma unroll
                for (int j = 0; j < 4; j++)
                    acc[i][j] += a[i] * b[j];
        }
        __syncthreads();
    }

    #pragma unroll
    for (int i = 0; i < 8; i++) {
        int r = row0 + ty * 8 + i;
        if (r >= M) continue;
        #pragma unroll
        for (int j = 0; j < 4; j++) {
            int c = col0 + tx * 4 + j;
            if (c >= N) continue;
            float v = acc[i][j] + (bias ? bias[c] : 0.f);
            if (RELU) v = fmaxf(v, 0.f);
            C[(size_t)r * N + c] = v;
        }
    }
}

// ---------------- CSR build ----------------
__global__ void count_kernel(const int* __restrict__ ei) {
    int e = blockIdx.x * 256 + threadIdx.x;
    if (e < N_EDGES) {
        atomicAdd(&g_zs.cnt[ei[e]], 1);
        atomicAdd(&g_zs.cnt[ei[N_EDGES + e]], 1);
    }
}

__global__ void scan_kernel() {
    const int CH = (N_NODES + 1023) / 1024;  // 20
    __shared__ int ssum[1024];
    int tid = threadIdx.x;
    int begin = tid * CH;
    int endi = begin + CH; if (endi > N_NODES) endi = N_NODES;
    int s = 0;
    for (int i = begin; i < endi; i++) s += g_zs.cnt[i];
    ssum[tid] = s;
    __syncthreads();
    for (int off = 1; off < 1024; off <<= 1) {
        int v = 0;
        if (tid >= off) v = ssum[tid - off];
        __syncthreads();
        ssum[tid] += v;
        __syncthreads();
    }
    int run = ssum[tid] - s;
    for (int i = begin; i < endi; i++) {
        g_off[i] = run;
        g_cur[i] = run;
        run += g_zs.cnt[i];
    }
    if (tid == 1023) g_off[N_NODES] = ssum[1023];
}

__global__ void fill_kernel(const int* __restrict__ ei) {
    int e = blockIdx.x * 256 + threadIdx.x;
    if (e < N_EDGES) {
        int s = ei[e], d = ei[N_EDGES + e];
        int p = atomicAdd(&g_cur[s], 1);
        g_incid[p] = (e << 1);
        int p2 = atomicAdd(&g_cur[d], 1);
        g_incid[p2] = (e << 1) | 1;
    }
}

// ---------------- combined weights: Wc = Wab @ Win2, bc = Wab @ bin2 -----
__global__ __launch_bounds__(256)
void wc_kernel(const float* __restrict__ Wm1,
               const float* __restrict__ Win2,
               const float* __restrict__ bin2)
{
    __shared__ float part[256];
    __shared__ float bpart[64];
    int i = blockIdx.x;                  // 0..127
    const float* wrow = (i < 64) ? &Wm1[i * 512] : &Wm1[(i - 64) * 512 + 256];
    int t = threadIdx.x;
    int mh = t & 63, kq = t >> 6;
    float s = 0.f;
    #pragma unroll 16
    for (int k = kq * 64; k < kq * 64 + 64; k++)
        s += wrow[k] * Win2[k * 64 + mh];
    part[t] = s;
    if (kq == 0) {
        float b = 0.f;
        #pragma unroll
        for (int k = mh * 4; k < mh * 4 + 4; k++) b += wrow[k] * bin2[k];
        bpart[mh] = b;
    }
    __syncthreads();
    if (kq == 0)
        g_Wc[i * 64 + mh] = part[mh] + part[64 + mh] + part[128 + mh] + part[192 + mh];
    if (t == 0) {
        float bb = 0.f;
        #pragma unroll
        for (int k = 0; k < 64; k++) bb += bpart[k];
        g_bc[i] = bb;
    }
}

// ---------------- per-edge: t1/t2 -> Fs,Ft -> Q stored; P,S atomically into D
// Wm2 staged ONCE per block in shared, layout W4s[k/4][o][4] so the inner
// loop is two conflict-free LDS.128 per k-chunk (was 16-line-splayed LDG.128).
__global__ __launch_bounds__(256)
void edge_kernel(const int* __restrict__ ei, const float* __restrict__ Wm2,
                 const float* __restrict__ bm1, const float* __restrict__ bm2)
{
    __shared__ float W4s[1024];      // Wm2 repacked: [(k>>2)][o][k&3]
    __shared__ float bm2s[16];
    __shared__ float sbuf[8 * 160];  // per warp: t1[64] t2[64] fsft[32]
    int tid = threadIdx.x;
    for (int idx = tid; idx < 1024; idx += 256) {
        int o = idx >> 6, k = idx & 63;
        W4s[((k >> 2) << 6) + (o << 2) + (k & 3)] = Wm2[idx];
    }
    if (tid < 16) bm2s[tid] = bm2[tid];
    __syncthreads();

    int warp = tid >> 5, lane = tid & 31;
    int e = blockIdx.x * 8 + warp;   // grid 25000, exact
    float* sw = &sbuf[warp * 160];

    int s = ei[e], d = ei[N_EDGES + e];
    int k0 = lane * 2;
    float2 As = *(const float2*)&g_AB[s * 128 + k0];
    float2 Bd = *(const float2*)&g_AB[d * 128 + 64 + k0];
    float2 Ad = *(const float2*)&g_AB[d * 128 + k0];
    float2 Bs = *(const float2*)&g_AB[s * 128 + 64 + k0];
    float2 b1 = *(const float2*)&bm1[k0];
    sw[k0]          = fmaxf(As.x + Bd.x + b1.x, 0.f);
    sw[k0 + 1]      = fmaxf(As.y + Bd.y + b1.y, 0.f);
    sw[64 + k0]     = fmaxf(Ad.x + Bs.x + b1.x, 0.f);
    sw[64 + k0 + 1] = fmaxf(Ad.y + Bs.y + b1.y, 0.f);
    __syncwarp();

    // lanes 0-15 -> fs[o] from t1; lanes 16-31 -> ft[o] from t2
    int o = lane & 15;
    const float* tv = sw + ((lane >> 4) << 6);
    float accf = 0.f;
    #pragma unroll
    for (int kc = 0; kc < 16; kc++) {
        float4 t = *(const float4*)&tv[kc * 4];
        float4 w = *(const float4*)&W4s[kc * 64 + o * 4];
        accf += t.x * w.x + t.y * w.y + t.z * w.z + t.w * w.w;
    }
    accf += bm2s[o];
    sw[128 + lane] = accf;
    __syncwarp();

    if (lane < 16) {
        int i = lane >> 2, j = lane & 3;
        float p = 0.f, q = 0.f, ss = 0.f;
        #pragma unroll
        for (int m = 0; m < 4; m++) {
            float fsi = sw[128 + m * 4 + i], fsj = sw[128 + m * 4 + j];
            float fti = sw[144 + m * 4 + i], ftj = sw[144 + m * 4 + j];
            p  += fsi * fsj;   // P = Fs^T Fs
            q  += fsi * ftj;   // Q = Fs^T Ft
            ss += fti * ftj;   // S = Ft^T Ft
        }
        g_Q[(size_t)e * 16 + lane] = q;
        atomicAdd(&g_zs.D[s * 16 + lane], p);
        atomicAdd(&g_zs.D[d * 16 + lane], ss);
    }
}

// ---------------- per-node H = (Wd1^T @ xb) @ Wd2^T ----------------
__global__ __launch_bounds__(256)
void hcomp_kernel(const float* __restrict__ Wd1, const float* __restrict__ Wd2,
                  int layer)
{
    __shared__ float w2t[64][66];
    __shared__ float h1s[8][4][64];
    int tid = threadIdx.x;
    for (int idx = tid; idx < 4096; idx += 256) {
        int g = idx >> 6, f = idx & 63;
        w2t[f][g] = Wd2[layer * 4096 + idx];
    }
    float wd1[16];
    #pragma unroll
    for (int i = 0; i < 16; i++) wd1[i] = __ldg(&Wd1[layer * 16 + i]);

    int warp = tid >> 5, lane = tid & 31;
    int n = blockIdx.x * 8 + warp;   // grid 2500, exact
    int c0 = lane * 2;
    float2 xv[4];
    #pragma unroll
    for (int j = 0; j < 4; j++)
        xv[j] = *(const float2*)&g_h[n * 256 + j * 64 + c0];
    #pragma unroll
    for (int i = 0; i < 4; i++) {
        h1s[warp][i][c0]     = wd1[i] * xv[0].x + wd1[4 + i] * xv[1].x +
                               wd1[8 + i] * xv[2].x + wd1[12 + i] * xv[3].x;
        h1s[warp][i][c0 + 1] = wd1[i] * xv[0].y + wd1[4 + i] * xv[1].y +
                               wd1[8 + i] * xv[2].y + wd1[12 + i] * xv[3].y;
    }
    __syncthreads();

    float2 acc[4] = {{0,0},{0,0},{0,0},{0,0}};
    #pragma unroll
    for (int f = 0; f < 64; f++) {
        float2 w = *(const float2*)&w2t[f][c0];
        #pragma unroll
        for (int k = 0; k < 4; k++) {
            float hv = h1s[warp][k][f];
            acc[k].x += hv * w.x;
            acc[k].y += hv * w.y;
        }
    }
    #pragma unroll
    for (int k = 0; k < 4; k++)
        *(float2*)&g_H[n * 256 + k * 64 + c0] = acc[k];
}

// ---------------- gather: one incidence contribution -> acc -= Qeff @ H[other]
__device__ __forceinline__ void proc_inc(int idx, const int* __restrict__ ei,
                                         int c0, float2 acc[4])
{
    int v = __ldg(&g_incid[idx]);
    int e = v >> 1, role = v & 1;
    int other = __ldg(&ei[role ? e : (N_EDGES + e)]);
    const float4* qq = (const float4*)&g_Q[(size_t)e * 16];
    float4 Q0 = qq[0], Q1 = qq[1], Q2 = qq[2], Q3 = qq[3];
    float q00 = Q0.x, q11 = Q1.y, q22 = Q2.z, q33 = Q3.w;
    float q01 = role ? Q1.x : Q0.y;
    float q10 = role ? Q0.y : Q1.x;
    float q02 = role ? Q2.x : Q0.z;
    float q20 = role ? Q0.z : Q2.x;
    float q03 = role ? Q3.x : Q0.w;
    float q30 = role ? Q0.w : Q3.x;
    float q12 = role ? Q2.y : Q1.z;
    float q21 = role ? Q1.z : Q2.y;
    float q13 = role ? Q3.y : Q1.w;
    float q31 = role ? Q1.w : Q3.y;
    float q23 = role ? Q3.z : Q2.w;
    float q32 = role ? Q2.w : Q3.z;

    const float* hb = &g_H[(size_t)other * 256 + c0];
    float2 h0 = *(const float2*)&hb[0];
    float2 h1 = *(const float2*)&hb[64];
    float2 h2 = *(const float2*)&hb[128];
    float2 h3 = *(const float2*)&hb[192];

    acc[0].x -= q00*h0.x + q01*h1.x + q02*h2.x + q03*h3.x;
    acc[0].y -= q00*h0.y + q01*h1.y + q02*h2.y + q03*h3.y;
    acc[1].x -= q10*h0.x + q11*h1.x + q12*h2.x + q13*h3.x;
    acc[1].y -= q10*h0.y + q11*h1.y + q12*h2.y + q13*h3.y;
    acc[2].x -= q20*h0.x + q21*h1.x + q22*h2.x + q23*h3.x;
    acc[2].y -= q20*h0.y + q21*h1.y + q22*h2.y + q23*h3.y;
    acc[3].x -= q30*h0.x + q31*h1.x + q32*h2.x + q33*h3.x;
    acc[3].y -= q30*h0.y + q31*h1.y + q32*h2.y + q33*h3.y;
}

__global__ __launch_bounds__(256)
void gather_kernel(const int* __restrict__ ei)
{
    __shared__ float red[4][256];
    int warp = threadIdx.x >> 5, lane = threadIdx.x & 31;
    int slot = warp >> 1, w2 = warp & 1;
    int n = blockIdx.x * 4 + slot;   // grid 5000, exact
    int beg = g_off[n], endi = g_off[n + 1];
    int cnt = endi - beg;
    int mid = beg + ((cnt + 1) >> 1);
    int lo = w2 ? mid : beg;
    int hi = w2 ? endi : mid;
    int c0 = lane * 2;

    float2 acc[4] = {{0,0},{0,0},{0,0},{0,0}};

    int idx = lo;
    for (; idx + 1 < hi; idx += 2) {
        proc_inc(idx,     ei, c0, acc);
        proc_inc(idx + 1, ei, c0, acc);
    }
    if (idx < hi) proc_inc(idx, ei, c0, acc);

    if (w2) {
        #pragma unroll
        for (int k = 0; k < 4; k++) {
            red[slot][k * 64 + c0]     = acc[k].x;
            red[slot][k * 64 + c0 + 1] = acc[k].y;
        }
    }
    __syncthreads();
    if (!w2) {
        const float4* Dp = (const float4*)&g_zs.D[n * 16];
        float4 D0 = Dp[0], D1 = Dp[1], D2 = Dp[2], D3 = Dp[3];
        const float* hnb = &g_H[(size_t)n * 256 + c0];
        float2 hn0 = *(const float2*)&hnb[0];
        float2 hn1 = *(const float2*)&hnb[64];
        float2 hn2 = *(const float2*)&hnb[128];
        float2 hn3 = *(const float2*)&hnb[192];
        float4 Dk[4] = {D0, D1, D2, D3};
        #pragma unroll
        for (int k = 0; k < 4; k++) {
            float lx = acc[k].x + red[slot][k * 64 + c0]
                     + Dk[k].x*hn0.x + Dk[k].y*hn1.x + Dk[k].z*hn2.x + Dk[k].w*hn3.x;
            float ly = acc[k].y + red[slot][k * 64 + c0 + 1]
                     + Dk[k].x*hn0.y + Dk[k].y*hn1.y + Dk[k].z*hn2.y + Dk[k].w*hn3.y;
            float* xp = &g_h[(size_t)n * 256 + k * 64 + c0];
            float2 xv = *(const float2*)xp;
            xv.x -= fmaxf(lx, 0.f);
            xv.y -= fmaxf(ly, 0.f);
            *(float2*)xp = xv;
        }
    }
}

// ---------------- launch ----------------
extern "C" void kernel_launch(void* const* d_in, const int* in_sizes, int n_in,
                              void* d_out, int out_size)
{
    const float* x    = (const float*)d_in[0];
    const int*   ei   = (const int*)  d_in[1];
    const float* Win1 = (const float*)d_in[2];
    const float* bin1 = (const float*)d_in[3];
    const float* Win2 = (const float*)d_in[4];
    const float* bin2 = (const float*)d_in[5];
    const float* Wm1  = (const float*)d_in[6];
    const float* bm1  = (const float*)d_in[7];
    const float* Wm2  = (const float*)d_in[8];
    const float* bm2  = (const float*)d_in[9];
    const float* Wd1  = (const float*)d_in[10];
    const float* Wd2  = (const float*)d_in[11];
    const float* Wo1  = (const float*)d_in[12];
    const float* bo1  = (const float*)d_in[13];
    const float* Wo2  = (const float*)d_in[14];
    const float* bo2  = (const float*)d_in[15];
    float* out = (float*)d_out;

    void *p_zs, *p_h, *p_h1, *p_AB, *p_Wc, *p_bc;
    cudaGetSymbolAddress(&p_zs, g_zs);
    cudaGetSymbolAddress(&p_h,  g_h);
    cudaGetSymbolAddress(&p_h1, g_h1);
    cudaGetSymbolAddress(&p_AB, g_AB);
    cudaGetSymbolAddress(&p_Wc, g_Wc);
    cudaGetSymbolAddress(&p_bc, g_bc);
    float* h   = (float*)p_h;
    float* h1  = (float*)p_h1;
    float* AB  = (float*)p_AB;
    float* Wc  = (float*)p_Wc;
    float* bc  = (float*)p_bc;

    const int MB = (N_NODES + 127) / 128;  // 157

    // slot 1: combined weights
    wc_kernel<<<128, 256>>>(Wm1, Win2, bin2);
    // slot 2: h1 = relu(x@Win1^T + bin1)
    sgemm128<true ><<<dim3(1, MB), 256>>>(x, Win1, bin1, h1, N_NODES, 64, IN_DIM);
    // slot 3: zero cnt + D
    cudaMemsetAsync(p_zs, 0, sizeof(ZS), 0);
    // slot 4: AB = h1 @ Wc^T + bc
    sgemm128<false><<<dim3(2, MB), 256>>>(h1, Wc, bc, AB, N_NODES, 128, 64);
    // slot 5 (PROFILED): per-edge Q + D atomics
    edge_kernel<<<N_EDGES / 8, 256>>>(ei, Wm2, bm1, bm2);

    // CSR build
    count_kernel<<<(N_EDGES + 255) / 256, 256>>>(ei);
    scan_kernel<<<1, 1024>>>();
    fill_kernel<<<(N_EDGES + 255) / 256, 256>>>(ei);

    // h = h1@Win2^T + bin2
    sgemm128<false><<<dim3(4, MB), 256>>>(h1, Win2, bin2, h, N_NODES, 256, 64);

    // diffusion layers
    for (int l = 0; l < 2; l++) {
        hcomp_kernel<<<N_NODES / 8, 256>>>(Wd1, Wd2, l);
        gather_kernel<<<N_NODES / 4, 256>>>(ei);
    }

    // output MLP
    sgemm128<true ><<<dim3(1, MB), 256>>>(h,  Wo1, bo1, h1,  N_NODES, 64, 256);
    sgemm128<false><<<dim3(1, MB), 256>>>(h1, Wo2, bo2, out, N_NODES, 16, 64);
}